// round 6
// baseline (speedup 1.0000x reference)
#include <cuda_runtime.h>
#include <math.h>

// Sinkhorn distance, N=M=4096, D=256, EPS=0.1, 100 iterations.
// Persistent single-wave kernel; split u/v passes with warp-local reductions
// only. Log2-scaled throughout. R6: software-pipelined u-pass (depth-4
// register double buffer), dual online-LSE accumulators, tree-summed v-pass.

#define NN 4096
#define KK 256
#define SCALEF 14.4269504088896340736f   // log2(e)/EPS
#define NEG_BIG (-1e30f)
#define THREADS 1024
#define NBMAX 160
#define N_ITER 100

__device__ __align__(16) float g_C2[(size_t)NN * NN + 256]; // 64 MB (+ pad for prefetch)
__device__ __align__(16) float g_u[NN];
__device__ __align__(16) float g_v[NN];
__device__ float g_xs[NN];
__device__ float g_ys[NN];
__device__ double g_dpart[NBMAX];

__device__ unsigned g_bar_count;
__device__ volatile unsigned g_bar_gen;

__device__ __forceinline__ float ex2f(float x) {
    float r; asm("ex2.approx.ftz.f32 %0, %1;" : "=f"(r) : "f"(x)); return r;
}
__device__ __forceinline__ float lg2f(float x) {
    float r; asm("lg2.approx.ftz.f32 %0, %1;" : "=f"(r) : "f"(x)); return r;
}

__device__ __forceinline__ void grid_sync(int NB) {
    __syncthreads();
    if (threadIdx.x == 0) {
        unsigned gen = g_bar_gen;
        __threadfence();
        unsigned t = atomicAdd(&g_bar_count, 1u);
        if (t == (unsigned)(NB - 1)) {
            g_bar_count = 0;
            __threadfence();
            g_bar_gen = gen + 1;
        } else {
            while (g_bar_gen == gen) { }
        }
        __threadfence();
    }
    __syncthreads();
}

// online-LSE pairwise merge of (m,s) across the warp (5 shfl steps)
__device__ __forceinline__ void warp_lse_merge(float& m, float& s) {
    #pragma unroll
    for (int o = 16; o; o >>= 1) {
        float m2 = __shfl_xor_sync(0xffffffffu, m, o);
        float s2 = __shfl_xor_sync(0xffffffffu, s, o);
        float M = fmaxf(m, m2);
        s = s * ex2f(m - M) + s2 * ex2f(m2 - M);
        m = M;
    }
}

// ---------------------------------------------------------------------------
__global__ __launch_bounds__(256) void sqnorm_kernel(const float* __restrict__ X,
                                                     const float* __restrict__ Y) {
    int gw = (blockIdx.x * 256 + threadIdx.x) >> 5;
    int lane = threadIdx.x & 31;
    const float* src = (gw < NN) ? (X + (size_t)gw * KK) : (Y + (size_t)(gw - NN) * KK);
    float s = 0.f;
    #pragma unroll
    for (int c = 0; c < KK; c += 32) {
        float a = src[c + lane];
        s = fmaf(a, a, s);
    }
    #pragma unroll
    for (int o = 16; o; o >>= 1) s += __shfl_xor_sync(0xffffffffu, s, o);
    if (lane == 0) {
        if (gw < NN) g_xs[gw] = s; else g_ys[gw - NN] = s;
    }
}

__global__ void init_kernel() {
    int i = blockIdx.x * 256 + threadIdx.x;
    if (i < NN) g_v[i] = 0.f;
    if (i == 0) { g_bar_count = 0; g_bar_gen = 0; }
}

// ---------------------------------------------------------------------------
// C2[i][j] = (|x_i|^2 + |y_j|^2 - 2 x_i . y_j) * SCALEF  (fp32 FFMA GEMM)
__global__ __launch_bounds__(256) void gemm_kernel(const float* __restrict__ X,
                                                   const float* __restrict__ Y) {
    __shared__ float As[8][128];
    __shared__ float Bs[8][128];
    const int tid = threadIdx.x;
    const int bx = blockIdx.x;
    const int by = blockIdx.y;
    const int ar = tid >> 1;
    const int ak = (tid & 1) * 4;
    const int tx = tid & 15;
    const int ty = tid >> 4;

    const float* xp = X + (size_t)(by * 128 + ar) * KK + ak;
    const float* yp = Y + (size_t)(bx * 128 + ar) * KK + ak;

    float acc[8][8];
    #pragma unroll
    for (int i = 0; i < 8; ++i)
        #pragma unroll
        for (int j = 0; j < 8; ++j) acc[i][j] = 0.f;

    for (int kt = 0; kt < KK; kt += 8) {
        float4 av = *(const float4*)(xp + kt);
        float4 bv = *(const float4*)(yp + kt);
        __syncthreads();
        As[ak + 0][ar] = av.x; As[ak + 1][ar] = av.y;
        As[ak + 2][ar] = av.z; As[ak + 3][ar] = av.w;
        Bs[ak + 0][ar] = bv.x; Bs[ak + 1][ar] = bv.y;
        Bs[ak + 2][ar] = bv.z; Bs[ak + 3][ar] = bv.w;
        __syncthreads();
        #pragma unroll
        for (int k = 0; k < 8; ++k) {
            float a[8], b[8];
            *(float4*)(a)     = *(const float4*)&As[k][ty * 8];
            *(float4*)(a + 4) = *(const float4*)&As[k][ty * 8 + 4];
            *(float4*)(b)     = *(const float4*)&Bs[k][tx * 8];
            *(float4*)(b + 4) = *(const float4*)&Bs[k][tx * 8 + 4];
            #pragma unroll
            for (int i = 0; i < 8; ++i)
                #pragma unroll
                for (int j = 0; j < 8; ++j)
                    acc[i][j] = fmaf(a[i], b[j], acc[i][j]);
        }
    }

    const int gi0 = by * 128 + ty * 8;
    const int gj0 = bx * 128 + tx * 8;
    float yv[8];
    #pragma unroll
    for (int j = 0; j < 8; ++j) yv[j] = g_ys[gj0 + j];
    #pragma unroll
    for (int i = 0; i < 8; ++i) {
        float xs = g_xs[gi0 + i];
        float4 o0, o1;
        o0.x = (xs + yv[0] - 2.f * acc[i][0]) * SCALEF;
        o0.y = (xs + yv[1] - 2.f * acc[i][1]) * SCALEF;
        o0.z = (xs + yv[2] - 2.f * acc[i][2]) * SCALEF;
        o0.w = (xs + yv[3] - 2.f * acc[i][3]) * SCALEF;
        o1.x = (xs + yv[4] - 2.f * acc[i][4]) * SCALEF;
        o1.y = (xs + yv[5] - 2.f * acc[i][5]) * SCALEF;
        o1.z = (xs + yv[6] - 2.f * acc[i][6]) * SCALEF;
        o1.w = (xs + yv[7] - 2.f * acc[i][7]) * SCALEF;
        float* dst = g_C2 + (size_t)(gi0 + i) * NN + gj0;
        *(float4*)(dst)     = o0;
        *(float4*)(dst + 4) = o1;
    }
}

// ---------------------------------------------------------------------------
__global__ __launch_bounds__(THREADS, 1) void sinkhorn_persistent(int NB, float* __restrict__ out) {
    const int tid = threadIdx.x;
    const int bid = blockIdx.x;
    const int lane = tid & 31;
    const int wid = tid >> 5;

    __shared__ float svec[NN];          // 16 KB: v (u-pass) / u (v-pass) cache
    __shared__ float sm_m[32][33];
    __shared__ float sm_s[32][33];
    __shared__ float sred[32];

    for (int it = 0; it < N_ITER; ++it) {
        // ---- u-pass: warp-per-row, pipelined loads, dual accumulators ----
        for (int i = tid; i < NN; i += THREADS) svec[i] = g_v[i];
        __syncthreads();

        for (int row = bid + wid * NB; row < NN; row += 32 * NB) {
            const float4* Cp = (const float4*)(g_C2 + (size_t)row * NN) + lane;
            const float4* Vp = (const float4*)svec + lane;
            float m0 = NEG_BIG, s0 = 0.f;
            float m1 = NEG_BIG, s1 = 0.f;
            float4 c[4], n[4];
            #pragma unroll
            for (int k = 0; k < 4; ++k) c[k] = __ldg(Cp + (k << 5));
            #pragma unroll
            for (int blk = 0; blk < 8; ++blk) {
                if (blk < 7) {
                    #pragma unroll
                    for (int k = 0; k < 4; ++k)
                        n[k] = __ldg(Cp + (((blk + 1) * 4 + k) << 5));
                }
                #pragma unroll
                for (int k = 0; k < 4; ++k) {
                    float4 V4 = Vp[((blk * 4 + k) << 5)];
                    float t0 = V4.x - c[k].x, t1 = V4.y - c[k].y;
                    float t2 = V4.z - c[k].z, t3 = V4.w - c[k].w;
                    float mc = fmaxf(fmaxf(t0, t1), fmaxf(t2, t3));
                    if (k & 1) {
                        if (mc > m1) { s1 *= ex2f(m1 - mc); m1 = mc; }
                        s1 += (ex2f(t0 - m1) + ex2f(t1 - m1))
                            + (ex2f(t2 - m1) + ex2f(t3 - m1));
                    } else {
                        if (mc > m0) { s0 *= ex2f(m0 - mc); m0 = mc; }
                        s0 += (ex2f(t0 - m0) + ex2f(t1 - m0))
                            + (ex2f(t2 - m0) + ex2f(t3 - m0));
                    }
                }
                #pragma unroll
                for (int k = 0; k < 4; ++k) c[k] = n[k];
            }
            float M = fmaxf(m0, m1);
            float s = s0 * ex2f(m0 - M) + s1 * ex2f(m1 - M);
            warp_lse_merge(M, s);
            if (lane == 0) g_u[row] = -(M + lg2f(s));
        }
        grid_sync(NB);

        // ---- v-pass: CTA bid owns 32 columns; coalesced column sweep ----
        for (int i = tid; i < NN; i += THREADS) svec[i] = g_u[i];
        __syncthreads();
        for (int g = bid; g < NN / 32; g += NB) {
            const int c = lane;
            const int r = wid;
            const int col = (g << 5) + c;
            float m = NEG_BIG, s = 0.f;
            for (int q0 = 0; q0 < NN; q0 += 512) {
                const float* p = g_C2 + (size_t)(q0 + r) * NN + col;
                const float* up = &svec[q0 + r];
                float t[16];
                #pragma unroll
                for (int k = 0; k < 16; ++k)
                    t[k] = up[k << 5] - __ldg(p + ((size_t)k << 5) * NN);
                float mc = t[0];
                #pragma unroll
                for (int k = 1; k < 16; ++k) mc = fmaxf(mc, t[k]);
                if (mc > m) { s *= ex2f(m - mc); m = mc; }
                float e[16];
                #pragma unroll
                for (int k = 0; k < 16; ++k) e[k] = ex2f(t[k] - m);
                #pragma unroll
                for (int o = 1; o < 16; o <<= 1)
                    #pragma unroll
                    for (int k = 0; k < 16; k += 2 * o) e[k] += e[k + o];
                s += e[0];
            }
            sm_m[r][c] = m;
            sm_s[r][c] = s;
            __syncthreads();
            {   // warp wid merges the 32 strata of column wid
                float mm = sm_m[lane][wid];
                float ss = sm_s[lane][wid];
                warp_lse_merge(mm, ss);
                if (lane == 0) g_v[(g << 5) + wid] = -(mm + lg2f(ss));
            }
            __syncthreads();
        }
        grid_sync(NB);
    }

    // ---- final cost: sum P*C / N  (warp-per-row) ----
    {
        for (int i = tid; i < NN; i += THREADS) svec[i] = g_v[i];
        __syncthreads();
        float acc = 0.f;
        for (int row = bid + wid * NB; row < NN; row += 32 * NB) {
            const float u2 = g_u[row];
            const float* Crow = g_C2 + (size_t)row * NN;
            #pragma unroll 4
            for (int c0 = 0; c0 < NN; c0 += 128) {
                int cc = c0 + lane * 4;
                float4 C4 = __ldg((const float4*)(Crow + cc));
                float4 V4 = *(const float4*)&svec[cc];
                acc = fmaf(ex2f(u2 + V4.x - C4.x), C4.x, acc);
                acc = fmaf(ex2f(u2 + V4.y - C4.y), C4.y, acc);
                acc = fmaf(ex2f(u2 + V4.z - C4.z), C4.z, acc);
                acc = fmaf(ex2f(u2 + V4.w - C4.w), C4.w, acc);
            }
        }
        #pragma unroll
        for (int o = 16; o; o >>= 1) acc += __shfl_xor_sync(0xffffffffu, acc, o);
        __syncthreads();
        if (lane == 0) sred[wid] = acc;
        __syncthreads();
        if (wid == 0) {
            float s = sred[lane];
            #pragma unroll
            for (int o = 16; o; o >>= 1) s += __shfl_xor_sync(0xffffffffu, s, o);
            if (lane == 0) g_dpart[bid] = (double)s;
        }
        grid_sync(NB);
        if (bid == 0 && tid == 0) {
            double S = 0.0;
            for (int b = 0; b < NB; ++b) S += g_dpart[b];
            out[0] = (float)(S / ((double)SCALEF * (double)NN));
        }
    }
}

// ---------------------------------------------------------------------------
extern "C" void kernel_launch(void* const* d_in, const int* in_sizes, int n_in,
                              void* d_out, int out_size) {
    const float* x = (const float*)d_in[0];
    const float* y = (const float*)d_in[1];
    float* out = (float*)d_out;

    int dev = 0;
    cudaGetDevice(&dev);
    int sm = 148;
    cudaDeviceGetAttribute(&sm, cudaDevAttrMultiProcessorCount, dev);
    int NB = sm < NBMAX ? sm : NBMAX;

    sqnorm_kernel<<<1024, 256>>>(x, y);
    init_kernel<<<16, 256>>>();
    gemm_kernel<<<dim3(32, 32), 256>>>(x, y);
    sinkhorn_persistent<<<NB, THREADS>>>(NB, out);
}

// round 7
// speedup vs baseline: 1.0086x; 1.0086x over previous
#include <cuda_runtime.h>
#include <math.h>

// Sinkhorn distance, N=M=4096, D=256, EPS=0.1, 100 iterations.
// Persistent single-wave kernel; split u/v passes with warp-local reductions
// only. Log2-scaled throughout. R7: branchless online-LSE in both passes,
// 8-elem groups + dual accumulator streams in the u-pass.

#define NN 4096
#define KK 256
#define SCALEF 14.4269504088896340736f   // log2(e)/EPS
#define NEG_BIG (-1e30f)
#define THREADS 1024
#define NBMAX 160
#define N_ITER 100

__device__ __align__(16) float g_C2[(size_t)NN * NN];     // 64 MB: C * SCALEF
__device__ __align__(16) float g_u[NN];
__device__ __align__(16) float g_v[NN];
__device__ float g_xs[NN];
__device__ float g_ys[NN];
__device__ double g_dpart[NBMAX];

__device__ unsigned g_bar_count;
__device__ volatile unsigned g_bar_gen;

__device__ __forceinline__ float ex2f(float x) {
    float r; asm("ex2.approx.ftz.f32 %0, %1;" : "=f"(r) : "f"(x)); return r;
}
__device__ __forceinline__ float lg2f(float x) {
    float r; asm("lg2.approx.ftz.f32 %0, %1;" : "=f"(r) : "f"(x)); return r;
}

__device__ __forceinline__ void grid_sync(int NB) {
    __syncthreads();
    if (threadIdx.x == 0) {
        unsigned gen = g_bar_gen;
        __threadfence();
        unsigned t = atomicAdd(&g_bar_count, 1u);
        if (t == (unsigned)(NB - 1)) {
            g_bar_count = 0;
            __threadfence();
            g_bar_gen = gen + 1;
        } else {
            while (g_bar_gen == gen) { }
        }
        __threadfence();
    }
    __syncthreads();
}

// online-LSE pairwise merge of (m,s) across the warp (5 shfl steps)
__device__ __forceinline__ void warp_lse_merge(float& m, float& s) {
    #pragma unroll
    for (int o = 16; o; o >>= 1) {
        float m2 = __shfl_xor_sync(0xffffffffu, m, o);
        float s2 = __shfl_xor_sync(0xffffffffu, s, o);
        float M = fmaxf(m, m2);
        s = s * ex2f(m - M) + s2 * ex2f(m2 - M);
        m = M;
    }
}

// ---------------------------------------------------------------------------
__global__ __launch_bounds__(256) void sqnorm_kernel(const float* __restrict__ X,
                                                     const float* __restrict__ Y) {
    int gw = (blockIdx.x * 256 + threadIdx.x) >> 5;
    int lane = threadIdx.x & 31;
    const float* src = (gw < NN) ? (X + (size_t)gw * KK) : (Y + (size_t)(gw - NN) * KK);
    float s = 0.f;
    #pragma unroll
    for (int c = 0; c < KK; c += 32) {
        float a = src[c + lane];
        s = fmaf(a, a, s);
    }
    #pragma unroll
    for (int o = 16; o; o >>= 1) s += __shfl_xor_sync(0xffffffffu, s, o);
    if (lane == 0) {
        if (gw < NN) g_xs[gw] = s; else g_ys[gw - NN] = s;
    }
}

__global__ void init_kernel() {
    int i = blockIdx.x * 256 + threadIdx.x;
    if (i < NN) g_v[i] = 0.f;
    if (i == 0) { g_bar_count = 0; g_bar_gen = 0; }
}

// ---------------------------------------------------------------------------
// C2[i][j] = (|x_i|^2 + |y_j|^2 - 2 x_i . y_j) * SCALEF  (fp32 FFMA GEMM)
__global__ __launch_bounds__(256) void gemm_kernel(const float* __restrict__ X,
                                                   const float* __restrict__ Y) {
    __shared__ float As[8][128];
    __shared__ float Bs[8][128];
    const int tid = threadIdx.x;
    const int bx = blockIdx.x;
    const int by = blockIdx.y;
    const int ar = tid >> 1;
    const int ak = (tid & 1) * 4;
    const int tx = tid & 15;
    const int ty = tid >> 4;

    const float* xp = X + (size_t)(by * 128 + ar) * KK + ak;
    const float* yp = Y + (size_t)(bx * 128 + ar) * KK + ak;

    float acc[8][8];
    #pragma unroll
    for (int i = 0; i < 8; ++i)
        #pragma unroll
        for (int j = 0; j < 8; ++j) acc[i][j] = 0.f;

    for (int kt = 0; kt < KK; kt += 8) {
        float4 av = *(const float4*)(xp + kt);
        float4 bv = *(const float4*)(yp + kt);
        __syncthreads();
        As[ak + 0][ar] = av.x; As[ak + 1][ar] = av.y;
        As[ak + 2][ar] = av.z; As[ak + 3][ar] = av.w;
        Bs[ak + 0][ar] = bv.x; Bs[ak + 1][ar] = bv.y;
        Bs[ak + 2][ar] = bv.z; Bs[ak + 3][ar] = bv.w;
        __syncthreads();
        #pragma unroll
        for (int k = 0; k < 8; ++k) {
            float a[8], b[8];
            *(float4*)(a)     = *(const float4*)&As[k][ty * 8];
            *(float4*)(a + 4) = *(const float4*)&As[k][ty * 8 + 4];
            *(float4*)(b)     = *(const float4*)&Bs[k][tx * 8];
            *(float4*)(b + 4) = *(const float4*)&Bs[k][tx * 8 + 4];
            #pragma unroll
            for (int i = 0; i < 8; ++i)
                #pragma unroll
                for (int j = 0; j < 8; ++j)
                    acc[i][j] = fmaf(a[i], b[j], acc[i][j]);
        }
    }

    const int gi0 = by * 128 + ty * 8;
    const int gj0 = bx * 128 + tx * 8;
    float yv[8];
    #pragma unroll
    for (int j = 0; j < 8; ++j) yv[j] = g_ys[gj0 + j];
    #pragma unroll
    for (int i = 0; i < 8; ++i) {
        float xs = g_xs[gi0 + i];
        float4 o0, o1;
        o0.x = (xs + yv[0] - 2.f * acc[i][0]) * SCALEF;
        o0.y = (xs + yv[1] - 2.f * acc[i][1]) * SCALEF;
        o0.z = (xs + yv[2] - 2.f * acc[i][2]) * SCALEF;
        o0.w = (xs + yv[3] - 2.f * acc[i][3]) * SCALEF;
        o1.x = (xs + yv[4] - 2.f * acc[i][4]) * SCALEF;
        o1.y = (xs + yv[5] - 2.f * acc[i][5]) * SCALEF;
        o1.z = (xs + yv[6] - 2.f * acc[i][6]) * SCALEF;
        o1.w = (xs + yv[7] - 2.f * acc[i][7]) * SCALEF;
        float* dst = g_C2 + (size_t)(gi0 + i) * NN + gj0;
        *(float4*)(dst)     = o0;
        *(float4*)(dst + 4) = o1;
    }
}

// ---------------------------------------------------------------------------
__global__ __launch_bounds__(THREADS, 1) void sinkhorn_persistent(int NB, float* __restrict__ out) {
    const int tid = threadIdx.x;
    const int bid = blockIdx.x;
    const int lane = tid & 31;
    const int wid = tid >> 5;

    __shared__ float svec[NN];          // 16 KB: v (u-pass) / u (v-pass) cache
    __shared__ float sm_m[32][33];
    __shared__ float sm_s[32][33];
    __shared__ float sred[32];

    for (int it = 0; it < N_ITER; ++it) {
        // ---- u-pass: warp-per-row, branchless dual-stream online LSE ----
        for (int i = tid; i < NN; i += THREADS) svec[i] = g_v[i];
        __syncthreads();

        for (int row = bid + wid * NB; row < NN; row += 32 * NB) {
            const float4* Cp = (const float4*)(g_C2 + (size_t)row * NN) + lane;
            const float4* Vp = (const float4*)svec + lane;
            float m0 = NEG_BIG, s0 = 0.f;
            float m1 = NEG_BIG, s1 = 0.f;
            #pragma unroll
            for (int b = 0; b < 32; b += 4) {
                float4 Ca = __ldg(Cp + ((b + 0) << 5));
                float4 Cb = __ldg(Cp + ((b + 1) << 5));
                float4 Cc = __ldg(Cp + ((b + 2) << 5));
                float4 Cd = __ldg(Cp + ((b + 3) << 5));
                float4 Va = Vp[((b + 0) << 5)];
                float4 Vb = Vp[((b + 1) << 5)];
                float4 Vc = Vp[((b + 2) << 5)];
                float4 Vd = Vp[((b + 3) << 5)];
                // stream 0: chunks a,b (8 elems, one online step)
                {
                    float t0 = Va.x - Ca.x, t1 = Va.y - Ca.y;
                    float t2 = Va.z - Ca.z, t3 = Va.w - Ca.w;
                    float t4 = Vb.x - Cb.x, t5 = Vb.y - Cb.y;
                    float t6 = Vb.z - Cb.z, t7 = Vb.w - Cb.w;
                    float mc = fmaxf(fmaxf(fmaxf(t0, t1), fmaxf(t2, t3)),
                                     fmaxf(fmaxf(t4, t5), fmaxf(t6, t7)));
                    float mn = fmaxf(m0, mc);
                    float e = ((ex2f(t0 - mn) + ex2f(t1 - mn)) + (ex2f(t2 - mn) + ex2f(t3 - mn)))
                            + ((ex2f(t4 - mn) + ex2f(t5 - mn)) + (ex2f(t6 - mn) + ex2f(t7 - mn)));
                    s0 = s0 * ex2f(m0 - mn) + e;
                    m0 = mn;
                }
                // stream 1: chunks c,d
                {
                    float t0 = Vc.x - Cc.x, t1 = Vc.y - Cc.y;
                    float t2 = Vc.z - Cc.z, t3 = Vc.w - Cc.w;
                    float t4 = Vd.x - Cd.x, t5 = Vd.y - Cd.y;
                    float t6 = Vd.z - Cd.z, t7 = Vd.w - Cd.w;
                    float mc = fmaxf(fmaxf(fmaxf(t0, t1), fmaxf(t2, t3)),
                                     fmaxf(fmaxf(t4, t5), fmaxf(t6, t7)));
                    float mn = fmaxf(m1, mc);
                    float e = ((ex2f(t0 - mn) + ex2f(t1 - mn)) + (ex2f(t2 - mn) + ex2f(t3 - mn)))
                            + ((ex2f(t4 - mn) + ex2f(t5 - mn)) + (ex2f(t6 - mn) + ex2f(t7 - mn)));
                    s1 = s1 * ex2f(m1 - mn) + e;
                    m1 = mn;
                }
            }
            float M = fmaxf(m0, m1);
            float s = s0 * ex2f(m0 - M) + s1 * ex2f(m1 - M);
            warp_lse_merge(M, s);
            if (lane == 0) g_u[row] = -(M + lg2f(s));
        }
        grid_sync(NB);

        // ---- v-pass: CTA bid owns 32 columns; branchless online LSE ----
        for (int i = tid; i < NN; i += THREADS) svec[i] = g_u[i];
        __syncthreads();
        for (int g = bid; g < NN / 32; g += NB) {
            const int c = lane;
            const int r = wid;
            const int col = (g << 5) + c;
            float m = NEG_BIG, s = 0.f;
            for (int q0 = 0; q0 < NN; q0 += 512) {
                const float* p = g_C2 + (size_t)(q0 + r) * NN + col;
                const float* up = &svec[q0 + r];
                float t[16];
                #pragma unroll
                for (int k = 0; k < 16; ++k)
                    t[k] = up[k << 5] - __ldg(p + ((size_t)k << 5) * NN);
                float mc = t[0];
                #pragma unroll
                for (int k = 1; k < 16; ++k) mc = fmaxf(mc, t[k]);
                float mn = fmaxf(m, mc);
                float e[16];
                #pragma unroll
                for (int k = 0; k < 16; ++k) e[k] = ex2f(t[k] - mn);
                #pragma unroll
                for (int o = 1; o < 16; o <<= 1)
                    #pragma unroll
                    for (int k = 0; k < 16; k += 2 * o) e[k] += e[k + o];
                s = s * ex2f(m - mn) + e[0];
                m = mn;
            }
            sm_m[r][c] = m;
            sm_s[r][c] = s;
            __syncthreads();
            {   // warp wid merges the 32 strata of column wid
                float mm = sm_m[lane][wid];
                float ss = sm_s[lane][wid];
                warp_lse_merge(mm, ss);
                if (lane == 0) g_v[(g << 5) + wid] = -(mm + lg2f(ss));
            }
            __syncthreads();
        }
        grid_sync(NB);
    }

    // ---- final cost: sum P*C / N  (warp-per-row) ----
    {
        for (int i = tid; i < NN; i += THREADS) svec[i] = g_v[i];
        __syncthreads();
        float acc = 0.f;
        for (int row = bid + wid * NB; row < NN; row += 32 * NB) {
            const float u2 = g_u[row];
            const float* Crow = g_C2 + (size_t)row * NN;
            #pragma unroll 4
            for (int c0 = 0; c0 < NN; c0 += 128) {
                int cc = c0 + lane * 4;
                float4 C4 = __ldg((const float4*)(Crow + cc));
                float4 V4 = *(const float4*)&svec[cc];
                acc = fmaf(ex2f(u2 + V4.x - C4.x), C4.x, acc);
                acc = fmaf(ex2f(u2 + V4.y - C4.y), C4.y, acc);
                acc = fmaf(ex2f(u2 + V4.z - C4.z), C4.z, acc);
                acc = fmaf(ex2f(u2 + V4.w - C4.w), C4.w, acc);
            }
        }
        #pragma unroll
        for (int o = 16; o; o >>= 1) acc += __shfl_xor_sync(0xffffffffu, acc, o);
        __syncthreads();
        if (lane == 0) sred[wid] = acc;
        __syncthreads();
        if (wid == 0) {
            float s = sred[lane];
            #pragma unroll
            for (int o = 16; o; o >>= 1) s += __shfl_xor_sync(0xffffffffu, s, o);
            if (lane == 0) g_dpart[bid] = (double)s;
        }
        grid_sync(NB);
        if (bid == 0 && tid == 0) {
            double S = 0.0;
            for (int b = 0; b < NB; ++b) S += g_dpart[b];
            out[0] = (float)(S / ((double)SCALEF * (double)NN));
        }
    }
}

// ---------------------------------------------------------------------------
extern "C" void kernel_launch(void* const* d_in, const int* in_sizes, int n_in,
                              void* d_out, int out_size) {
    const float* x = (const float*)d_in[0];
    const float* y = (const float*)d_in[1];
    float* out = (float*)d_out;

    int dev = 0;
    cudaGetDevice(&dev);
    int sm = 148;
    cudaDeviceGetAttribute(&sm, cudaDevAttrMultiProcessorCount, dev);
    int NB = sm < NBMAX ? sm : NBMAX;

    sqnorm_kernel<<<1024, 256>>>(x, y);
    init_kernel<<<16, 256>>>();
    gemm_kernel<<<dim3(32, 32), 256>>>(x, y);
    sinkhorn_persistent<<<NB, THREADS>>>(NB, out);
}